// round 5
// baseline (speedup 1.0000x reference)
#include <cuda_runtime.h>
#include <cuda_bf16.h>
#include <stdint.h>

// RayCastLayer via Toeplitz line-transform factorization (R5: single-wave +
// instruction-diet round).
// out = V + H + D1 + D2; 4 planes per CTA as one float4 stream; FFMA2 packs
// 2 planes/instr; each thread register-tiles 4 outputs along its line and
// runs TWO families back-to-back (A: V,D1  B: H,D2) into 4 partial buffers.
// Weights pre-packed as duplicated f32 pairs so the hot loop has zero movs.

#define BOARD 19
#define NPOS  361
#define PW    55            // padded tile width (x shifted by +18)
#define TILE  (BOARD * PW)  // 1045 float4 entries
#define PLANES 4
#define THREADS 256

__device__ __forceinline__ uint32_t smem_addr(const void* p) {
    return (uint32_t)__cvta_generic_to_shared(p);
}

// One line-transform pass: 19 k-steps, 4 outputs x 4 planes.
// STRIDE (float4 units) compile-time -> LDS immediate offsets.
// Weight row = 20 packed pairs = 160B; aw points at pair y0 (16B aligned).
template <int STRIDE>
__device__ __forceinline__ void pass4(uint32_t a0, uint32_t aw,
                                      unsigned long long acc[8])
{
    #pragma unroll
    for (int k = 0; k < BOARD; k++) {
        unsigned long long va, vb, w0, w1, w2, w3;
        asm volatile("ld.shared.v2.b64 {%0,%1}, [%2];"
                     : "=l"(va), "=l"(vb) : "r"(a0 + k * (STRIDE * 16)));
        asm volatile("ld.shared.v2.b64 {%0,%1}, [%2];"
                     : "=l"(w0), "=l"(w1) : "r"(aw + k * 160));
        asm volatile("ld.shared.v2.b64 {%0,%1}, [%2];"
                     : "=l"(w2), "=l"(w3) : "r"(aw + k * 160 + 16));
        asm("fma.rn.f32x2 %0, %1, %2, %0;" : "+l"(acc[0]) : "l"(va), "l"(w0));
        asm("fma.rn.f32x2 %0, %1, %2, %0;" : "+l"(acc[1]) : "l"(vb), "l"(w0));
        asm("fma.rn.f32x2 %0, %1, %2, %0;" : "+l"(acc[2]) : "l"(va), "l"(w1));
        asm("fma.rn.f32x2 %0, %1, %2, %0;" : "+l"(acc[3]) : "l"(vb), "l"(w1));
        asm("fma.rn.f32x2 %0, %1, %2, %0;" : "+l"(acc[4]) : "l"(va), "l"(w2));
        asm("fma.rn.f32x2 %0, %1, %2, %0;" : "+l"(acc[5]) : "l"(vb), "l"(w2));
        asm("fma.rn.f32x2 %0, %1, %2, %0;" : "+l"(acc[6]) : "l"(va), "l"(w3));
        asm("fma.rn.f32x2 %0, %1, %2, %0;" : "+l"(acc[7]) : "l"(vb), "l"(w3));
    }
}

__device__ __forceinline__ unsigned long long dupf(float w) {
    unsigned long long u;
    const uint32_t b = __float_as_uint(w);
    asm("mov.b64 %0, {%1,%1};" : "=l"(u) : "r"(b));
    return u;
}

__global__ __launch_bounds__(THREADS, 4)
void raycast_kernel(const float* __restrict__ x,
                    const float* __restrict__ weight,
                    float* __restrict__ out,
                    int nplanes)
{
    __shared__ float4 t0[TILE];                       // padded [19][55] x 4 planes
    __shared__ ulonglong2 bufV[NPOS];                 // per-family partials
    __shared__ ulonglong2 bufH[NPOS];
    __shared__ ulonglong2 bufD1[NPOS];
    __shared__ ulonglong2 bufD2[NPOS];
    __shared__ __align__(16) unsigned long long wlp[BOARD * 20];  // WL^T dup pairs
    __shared__ __align__(16) unsigned long long wdp[BOARD * 20];  // WD^T dup pairs

    const int tid = threadIdx.x;
    const int g0  = blockIdx.x * PLANES;

    // ---- zero ONLY the lateral pad columns (no overlap with data fill) ----
    #pragma unroll
    for (int i = tid; i < BOARD * 36; i += THREADS) {
        const int y = i / 36;
        const int c = i - y * 36;
        const int col = (c < 18) ? c : (c + BOARD);   // cols [0,18) and [37,55)
        t0[y * PW + col] = make_float4(0.f, 0.f, 0.f, 0.f);
    }

    // ---- packed duplicated Toeplitz weights: [k][y] pairs, y padded to 20 ----
    #pragma unroll
    for (int i = tid; i < BOARD * 20; i += THREADS) {
        const int k = i / 20;
        const int y = i - k * 20;
        const int d = (k > y) ? (k - y) : (y - k);
        const bool v = (y < BOARD) && (d > 0);
        wlp[i] = dupf(v ? weight[d - 1]      : 0.0f);
        wdp[i] = dupf(v ? weight[18 + d - 1] : 0.0f);
    }

    // ---- data fill: per position, 4 planes -> one STS.128 ----
    const bool full = (g0 + PLANES <= nplanes);
    #pragma unroll
    for (int p = tid; p < NPOS; p += THREADS) {
        const int yy = p / BOARD;
        const int xx = p - yy * BOARD;
        float4 v;
        if (full) {
            v.x = x[(g0 + 0) * NPOS + p];
            v.y = x[(g0 + 1) * NPOS + p];
            v.z = x[(g0 + 2) * NPOS + p];
            v.w = x[(g0 + 3) * NPOS + p];
        } else {
            v.x = (g0 + 0 < nplanes) ? x[(g0 + 0) * NPOS + p] : 0.f;
            v.y = (g0 + 1 < nplanes) ? x[(g0 + 1) * NPOS + p] : 0.f;
            v.z = (g0 + 2 < nplanes) ? x[(g0 + 2) * NPOS + p] : 0.f;
            v.w = (g0 + 3 < nplanes) ? x[(g0 + 3) * NPOS + p] : 0.f;
        }
        t0[yy * PW + xx + 18] = v;
    }
    __syncthreads();

    const uint32_t t0a = smem_addr(t0);
    const uint32_t wla = smem_addr(wlp);
    const uint32_t wda = smem_addr(wdp);

    unsigned long long acc[8];

    if (tid < 128) {
        // ---- pass V: outputs (y0+r, xx), reads s[k][xx], stride PW ----
        if (tid < 95) {
            #pragma unroll
            for (int i = 0; i < 8; i++) acc[i] = 0ull;
            const int yg = tid / BOARD;
            const int xx = tid - yg * BOARD;
            const int y0 = 4 * yg;
            pass4<PW>(t0a + (xx + 18) * 16, wla + y0 * 8, acc);
            #pragma unroll
            for (int r = 0; r < 4; r++) {
                const int yy = y0 + r;
                if (yy < BOARD)
                    bufV[yy * BOARD + xx] = make_ulonglong2(acc[r*2+0], acc[r*2+1]);
            }
        }
        // ---- pass D1: outputs (y0+r, xb+r), stride PW+1 ----
        if (tid < 110) {
            #pragma unroll
            for (int i = 0; i < 8; i++) acc[i] = 0ull;
            const int yg = tid / 22;
            const int xb = (tid - yg * 22) - 3;
            const int y0 = 4 * yg;
            int b = xb - y0 + 18;
            if (b < 0) b = 0;                // only the fully-invalid corner thread
            pass4<PW + 1>(t0a + b * 16, wda + y0 * 8, acc);
            #pragma unroll
            for (int r = 0; r < 4; r++) {
                const int yy = y0 + r;
                const int xx = xb + r;
                if ((yy < BOARD) && (xx >= 0) && (xx < BOARD))
                    bufD1[yy * BOARD + xx] = make_ulonglong2(acc[r*2+0], acc[r*2+1]);
            }
        }
    } else {
        const int gt = tid - 128;
        // ---- pass H: outputs (yy, x0+r), reads s[yy][k], stride 1 ----
        if (gt < 95) {
            #pragma unroll
            for (int i = 0; i < 8; i++) acc[i] = 0ull;
            const int yy = gt / 5;
            const int xg = gt - yy * 5;
            const int x0 = 4 * xg;
            pass4<1>(t0a + (yy * PW + 18) * 16, wla + x0 * 8, acc);
            #pragma unroll
            for (int r = 0; r < 4; r++) {
                const int xx = x0 + r;
                if (xx < BOARD)
                    bufH[yy * BOARD + xx] = make_ulonglong2(acc[r*2+0], acc[r*2+1]);
            }
        }
        // ---- pass D2: outputs (y0+r, xb-r), stride PW-1 ----
        if (gt < 110) {
            #pragma unroll
            for (int i = 0; i < 8; i++) acc[i] = 0ull;
            const int yg = gt / 22;
            const int xb = gt - yg * 22;     // 0..21
            const int y0 = 4 * yg;
            const int b  = xb + y0 + 18;     // worst overflow reads zero pad
            pass4<PW - 1>(t0a + b * 16, wda + y0 * 8, acc);
            #pragma unroll
            for (int r = 0; r < 4; r++) {
                const int yy = y0 + r;
                const int xx = xb - r;
                if ((yy < BOARD) && (xx >= 0) && (xx < BOARD))
                    bufD2[yy * BOARD + xx] = make_ulonglong2(acc[r*2+0], acc[r*2+1]);
            }
        }
    }

    __syncthreads();

    // ---- combine 4 partials and store (coalesced per plane) ----
    #pragma unroll
    for (int p = tid; p < NPOS; p += THREADS) {
        const ulonglong2 A = bufV[p];
        const ulonglong2 B = bufH[p];
        const ulonglong2 C = bufD1[p];
        const ulonglong2 D = bufD2[p];
        unsigned long long s0 = A.x, s1 = A.y;
        asm("add.rn.f32x2 %0, %0, %1;" : "+l"(s0) : "l"(B.x));
        asm("add.rn.f32x2 %0, %0, %1;" : "+l"(s0) : "l"(C.x));
        asm("add.rn.f32x2 %0, %0, %1;" : "+l"(s0) : "l"(D.x));
        asm("add.rn.f32x2 %0, %0, %1;" : "+l"(s1) : "l"(B.y));
        asm("add.rn.f32x2 %0, %0, %1;" : "+l"(s1) : "l"(C.y));
        asm("add.rn.f32x2 %0, %0, %1;" : "+l"(s1) : "l"(D.y));
        uint32_t p0, p1, p2, p3;
        asm("mov.b64 {%0,%1}, %2;" : "=r"(p0), "=r"(p1) : "l"(s0));
        asm("mov.b64 {%0,%1}, %2;" : "=r"(p2), "=r"(p3) : "l"(s1));
        if (full) {
            out[(g0 + 0) * NPOS + p] = __uint_as_float(p0);
            out[(g0 + 1) * NPOS + p] = __uint_as_float(p1);
            out[(g0 + 2) * NPOS + p] = __uint_as_float(p2);
            out[(g0 + 3) * NPOS + p] = __uint_as_float(p3);
        } else {
            if (g0 + 0 < nplanes) out[(g0 + 0) * NPOS + p] = __uint_as_float(p0);
            if (g0 + 1 < nplanes) out[(g0 + 1) * NPOS + p] = __uint_as_float(p1);
            if (g0 + 2 < nplanes) out[(g0 + 2) * NPOS + p] = __uint_as_float(p2);
            if (g0 + 3 < nplanes) out[(g0 + 3) * NPOS + p] = __uint_as_float(p3);
        }
    }
}

extern "C" void kernel_launch(void* const* d_in, const int* in_sizes, int n_in,
                              void* d_out, int out_size)
{
    const float* x      = (const float*)d_in[0];   // [32,64,19,19]
    const float* weight = (const float*)d_in[1];   // [2,18]
    float* out          = (float*)d_out;

    const int nplanes = in_sizes[0] / NPOS;        // 2048
    const int grid = (nplanes + PLANES - 1) / PLANES;   // 512

    raycast_kernel<<<grid, THREADS>>>(x, weight, out, nplanes);
}